// round 13
// baseline (speedup 1.0000x reference)
#include <cuda_runtime.h>
#include <cuda_bf16.h>
#include <math.h>

#define GRID 148
#define TPB  512
#define NWPB (TPB/32)            /* 16 warps per block */
#define NWARP (GRID*NWPB)        /* 2368 */
#define NT    (GRID*TPB)         /* 75776 */

#define HD   512
#define D2   1024
#define D4   2048
#define VV   32000
#define MQ   32
#define NP   4096
#define LL   64
#define G6   (3*D4)              /* 6144 GRU gate rows */

// ---------------- device scratch (no allocation allowed) ----------------
__device__ __align__(16) float g_h[D2];
__device__ __align__(16) float g_hpart[GRID*D2];
__device__ __align__(16) float g_uah[D2];
__device__ __align__(16) float g_d[2][D4];
__device__ __align__(16) float g_r1[D2];
__device__ __align__(16) float g_rmax[HD];
__device__ __align__(16) float g_elog[VV];
__device__ __align__(16) float g_gx[LL*G6];     // precomputed W_ih[:, :D2]@w_t + b_ih  (1.57 MB)
__device__ __align__(16) float g_wrx[LL*D2];    // precomputed w_r@w_t                  (256 KB)
__device__ __align__(16) __nv_bfloat16 g_wo16[(size_t)VV*HD];   // 32.75 MB bf16 vocab weights
__device__ float g_spart2[2*GRID];
__device__ float g_bsum[GRID];
__device__ unsigned g_bar;

__global__ void init_bar_kernel() { g_bar = 0u; }

__device__ __forceinline__ float wredsum(float v) {
#pragma unroll
    for (int o = 16; o; o >>= 1) v += __shfl_xor_sync(0xffffffffu, v, o);
    return v;
}

// Grid barrier: release fence + arrive; poll with volatile load;
// acquire fence (gpu scope -> L1 invalidate) on depart.
__device__ __forceinline__ void gsync(unsigned phase) {
    __syncthreads();
    if (threadIdx.x == 0) {
        __threadfence();
        atomicAdd(&g_bar, 1u);
        const unsigned target = (unsigned)GRID * phase;
        while (*((volatile unsigned*)&g_bar) < target) __nanosleep(32);
        __threadfence();
    }
    __syncthreads();
}

// deterministic 148-wide sum on warp 0 (all lanes return full sum)
__device__ __forceinline__ float red148(const float* __restrict__ p, int lane) {
    float s = 0.f;
#pragma unroll
    for (int i = 0; i < 5; i++) { int idx = lane + 32*i; if (idx < GRID) s += p[idx]; }
    return wredsum(s);
}

#define FMA4(acc, a, b) (acc) += (a).x*(b).x + (a).y*(b).y + (a).z*(b).z + (a).w*(b).w

__global__ __launch_bounds__(TPB, 1)
void decoder_kernel(const float* __restrict__ h_q,   const float* __restrict__ h_p,
                    const float* __restrict__ ans,   const float* __restrict__ v_w,
                    const float* __restrict__ w_d_w, const float* __restrict__ w_d_b,
                    const float* __restrict__ w_a_w, const float* __restrict__ u_a_w,
                    const float* __restrict__ w_r_w, const float* __restrict__ u_r_w,
                    const float* __restrict__ v_r_w, const float* __restrict__ w_o_w,
                    const float* __restrict__ gwih,  const float* __restrict__ gwhh,
                    const float* __restrict__ gbih,  const float* __restrict__ gbhh,
                    float* __restrict__ out)
{
    const int tid  = threadIdx.x;
    const int lane = tid & 31;
    const int wid  = tid >> 5;
    const int bid  = blockIdx.x;
    const int gw   = bid * NWPB + wid;
    unsigned ph = 0;

    __shared__ float sh_part[384];
    __shared__ float sh_ws[NWPB];
    __shared__ float sh_a0, sh_a1, sh_inv;
    __shared__ __align__(16) float sh_rm[HD];

    // per-block output counts (grid-stride by block over output indices)
    const int n_k = (bid < 124) ? 14 : 13;   // GRU outputs   (2048)
    const int n_j = (bid < 136) ? 7  : 6;    // r1 / w_a rows (1024)
    const int n_m = (bid < 68)  ? 4  : 3;    // maxout outs   (512)

    // ================= Prologue =================
    // P1: h column partials + d0 + w_o->bf16 + ans-GEMM precompute
    {
        float acc0 = 0.f, acc1 = 0.f;
        const int c0 = tid, c1 = tid + TPB;
        for (int r = bid; r < MQ + NP; r += GRID) {
            const float* row = (r < MQ) ? (h_q + (size_t)r*D2) : (h_p + (size_t)(r - MQ)*D2);
            acc0 += row[c0];
            acc1 += row[c1];
        }
        g_hpart[bid*D2 + c0] = acc0;
        g_hpart[bid*D2 + c1] = acc1;
    }
    if (gw < 2*D2) {   // d0[i][j] = tanh(w_d_w[j] . src_i + b[j])
        const int i = gw >> 10, j = gw & (D2-1);
        const float4* src = (const float4*)(i == 0 ? h_q : h_p);
        const float4* wr  = (const float4*)(w_d_w + (size_t)j*D2);
        float s = 0.f;
        for (int q = lane; q < D2/4; q += 32) { float4 a = wr[q], b = src[q]; FMA4(s, a, b); }
        s = wredsum(s);
        if (lane == 0) g_d[0][i*D2 + j] = tanhf(s + w_d_b[j]);
    }
    for (int i = bid*TPB + tid; i < VV*HD/4; i += NT) {   // fp32 -> bf16
        float4 f = ((const float4*)w_o_w)[i];
        __nv_bfloat162 lo = __floats2bfloat162_rn(f.x, f.y);
        __nv_bfloat162 hi = __floats2bfloat162_rn(f.z, f.w);
        uint2 u; u.x = *(unsigned*)&lo; u.y = *(unsigned*)&hi;
        ((uint2*)g_wo16)[i] = u;
    }
    // Precompute g_gx / g_wrx: task = (row, 16-step t-chunk)
    {
        const float4* ans4 = (const float4*)ans;
        const int NG = G6*4, NW = D2*4;
        for (int T = gw; T < NG + NW; T += NWARP) {
            const bool isg = (T < NG);
            const int  T2  = isg ? T : (T - NG);
            const int  row = T2 >> 2;
            const int  t0  = (T2 & 3) * 16;
            const float4* row4 = isg ? ((const float4*)gwih + (size_t)row*(D4/4))
                                     : ((const float4*)w_r_w + (size_t)row*(D2/4));
            float4 w[8];
#pragma unroll
            for (int j = 0; j < 8; j++) w[j] = row4[lane + 32*j];
#pragma unroll
            for (int tt = 0; tt < 16; tt++) {
                const int t = t0 + tt;
                const float4* a4 = ans4 + (size_t)t*(D2/4);
                float s = 0.f;
#pragma unroll
                for (int j = 0; j < 8; j++) { float4 b = a4[lane + 32*j]; FMA4(s, w[j], b); }
                s = wredsum(s);
                if (lane == 0) {
                    if (isg) g_gx[t*G6 + row] = s + gbih[row];
                    else     g_wrx[t*D2 + row] = s;
                }
            }
        }
    }
    gsync(++ph);

    // P2: reduce column partials -> g_h
    for (int j = bid*TPB + tid; j < D2; j += NT) {
        float s = 0.f;
        for (int b = 0; b < GRID; b++) s += g_hpart[b*D2 + j];
        g_h[j] = s;
    }
    gsync(++ph);

    // P3: u_a_h = u_a_w @ h
    if (gw < D2) {
        const float4* wr = (const float4*)(u_a_w + (size_t)gw*D2);
        const float4* hv = (const float4*)g_h;
        float s = 0.f;
        for (int q = lane; q < D2/4; q += 32) { float4 a = wr[q], b = hv[q]; FMA4(s, a, b); }
        s = wredsum(s);
        if (lane == 0) g_uah[gw] = s;
    }
    gsync(++ph);

    // P4: attention score partials for d0 -> g_spart2
    {
        float s0p = 0.f, s1p = 0.f;
        if (gw < D2) {
            const int j = gw;
            const float4* wa  = (const float4*)(w_a_w + (size_t)j*D2);
            const float4* dlo = (const float4*)g_d[0];
            const float4* dhi = dlo + 256;
            float a = 0.f, b = 0.f;
            for (int q = lane; q < 256; q += 32) {
                float4 w4 = wa[q], x = dlo[q], y = dhi[q];
                FMA4(a, w4, x); FMA4(b, w4, y);
            }
            a = wredsum(a); b = wredsum(b);
            if (lane == 0) {
                float uv = g_uah[j], vw0 = v_w[j];
                s0p = vw0 * tanhf(a + uv);
                s1p = vw0 * tanhf(b + uv);
            }
        }
        if (lane == 0) { sh_part[wid] = s0p; sh_part[32 + wid] = s1p; }
        __syncthreads();
        if (tid == 0) {
            float A = 0.f, B = 0.f;
            for (int k = 0; k < NWPB; k++) { A += sh_part[k]; B += sh_part[32 + k]; }
            g_spart2[bid] = A; g_spart2[GRID + bid] = B;
        }
    }
    gsync(++ph);

    // ============ decode loop: 2 grid barriers / step (software-pipelined) ============
    // Seg1(t) = [a-reduce + GRU/r1](t)  U  [vocab exp](t-1)
    // Seg2(t) = [v_r/maxout + attn scores](t)  U  [normalize+emit](t-1)
    int cur = 0;
    for (int t = 0; t <= LL; ++t) {
        const float*  dcur  = g_d[cur];
        const float4* dcur4 = (const float4*)dcur;
        float*        dnxt  = g_d[cur ^ 1];
        const float4* dnxt4 = (const float4*)dnxt;

        // ---------------- Seg1 ----------------
        if (t < LL && wid == 0) {
            float s0 = red148(g_spart2, lane);
            float s1 = red148(g_spart2 + GRID, lane);
            if (lane == 0) {
                float mx = fmaxf(s0, s1);
                float e0 = expf(s0 - mx), e1 = expf(s1 - mx);
                float inv = 1.f / (e0 + e1);
                sh_a0 = e0 * inv; sh_a1 = e1 * inv;
            }
        }
        if (t > 0) {
            for (int v = tid; v < HD; v += TPB) sh_rm[v] = g_rmax[v];
        }
        __syncthreads();
        const float a0 = sh_a0, a1 = sh_a1;

        if (t < LL) {   // GRU (c-half + hh gates) and u_r@c tasks
            const int totA = n_k*18 + n_j*2;
            for (int task = wid; task < totA; task += NWPB) {
                float s = 0.f;
                if (task < n_k*18) {
                    const int i = task / 18, sub = task - i*18;
                    const int g = sub / 6, sg = sub - g*6;
                    const int k = bid + i*GRID;
                    if (sg < 2) {   // W_ih row, c-half columns [1024,2048)
                        const float4* row4 = (const float4*)gwih + (size_t)(g*D4 + k)*(D4/4);
                        const int q0 = 256 + sg*128 + lane;
#pragma unroll
                        for (int it = 0; it < 4; it++) {
                            int q = q0 + 32*it; float4 w4 = row4[q];
                            float4 da = dcur4[q - 256], db = dcur4[q], b;
                            b.x = a0*da.x + a1*db.x; b.y = a0*da.y + a1*db.y;
                            b.z = a0*da.z + a1*db.z; b.w = a0*da.w + a1*db.w;
                            FMA4(s, w4, b);
                        }
                    } else {        // W_hh row, chunk sg-2
                        const float4* row4 = (const float4*)gwhh + (size_t)(g*D4 + k)*(D4/4);
                        const int q0 = (sg - 2)*128 + lane;
#pragma unroll
                        for (int it = 0; it < 4; it++) {
                            int q = q0 + 32*it; float4 w4 = row4[q], b = dcur4[q]; FMA4(s, w4, b);
                        }
                    }
                } else {            // u_r @ c
                    const int u = task - n_k*18, i = u >> 1, ch = u & 1;
                    const int j = bid + i*GRID;
                    const float4* row4 = (const float4*)u_r_w + (size_t)j*(D2/4);
                    const int q0 = ch*128 + lane;
#pragma unroll
                    for (int it = 0; it < 4; it++) {
                        int q = q0 + 32*it; float4 w4 = row4[q];
                        float4 da = dcur4[q], db = dcur4[q + 256], b;
                        b.x = a0*da.x + a1*db.x; b.y = a0*da.y + a1*db.y;
                        b.z = a0*da.z + a1*db.z; b.w = a0*da.w + a1*db.w;
                        FMA4(s, w4, b);
                    }
                }
                s = wredsum(s);
                if (lane == 0) sh_part[task] = s;
            }
        }
        __syncthreads();
        if (t < LL) {
            if (tid < n_k) {                      // fixed-order GRU combine
                const int k = bid + tid*GRID;
                const float* p = sh_part + tid*18;
                const float* gx = g_gx + t*G6;
                float i0 = gx[k]        + p[0]  + p[1];
                float h0 = p[2]+p[3]+p[4]+p[5]       + gbhh[k];
                float i1 = gx[D4 + k]   + p[6]  + p[7];
                float h1 = p[8]+p[9]+p[10]+p[11]     + gbhh[D4 + k];
                float i2 = gx[2*D4 + k] + p[12] + p[13];
                float h2 = p[14]+p[15]+p[16]+p[17]   + gbhh[2*D4 + k];
                float r = 1.f / (1.f + expf(-(i0 + h0)));
                float z = 1.f / (1.f + expf(-(i1 + h1)));
                float n = tanhf(i2 + r * h2);
                dnxt[k] = (1.f - z) * n + z * dcur[k];
            } else if (tid >= 64 && tid < 64 + n_j) {
                const int i = tid - 64, j = bid + i*GRID;
                const float* p = sh_part + n_k*18 + i*2;
                g_r1[j] = g_wrx[t*D2 + j] + p[0] + p[1];
            }
        }
        if (t > 0) {    // vocab logits (bf16) + exp + warp partial sums
            float4 ra0 = *(const float4*)(sh_rm + lane*8);
            float4 ra1 = *(const float4*)(sh_rm + lane*8 + 4);
            float4 rb0 = *(const float4*)(sh_rm + (lane + 32)*8);
            float4 rb1 = *(const float4*)(sh_rm + (lane + 32)*8 + 4);
            float psum = 0.f;
            for (int v = gw; v < VV; v += NWARP) {
                const uint4* wo4 = (const uint4*)(g_wo16 + (size_t)v*HD);
                uint4 ua = wo4[lane];
                uint4 ub = wo4[lane + 32];
                float s = 0.f;
                {
                    float2 f0 = __bfloat1622float2(*(__nv_bfloat162*)&ua.x);
                    float2 f1 = __bfloat1622float2(*(__nv_bfloat162*)&ua.y);
                    float2 f2 = __bfloat1622float2(*(__nv_bfloat162*)&ua.z);
                    float2 f3 = __bfloat1622float2(*(__nv_bfloat162*)&ua.w);
                    s += f0.x*ra0.x + f0.y*ra0.y + f1.x*ra0.z + f1.y*ra0.w
                       + f2.x*ra1.x + f2.y*ra1.y + f3.x*ra1.z + f3.y*ra1.w;
                }
                {
                    float2 f0 = __bfloat1622float2(*(__nv_bfloat162*)&ub.x);
                    float2 f1 = __bfloat1622float2(*(__nv_bfloat162*)&ub.y);
                    float2 f2 = __bfloat1622float2(*(__nv_bfloat162*)&ub.z);
                    float2 f3 = __bfloat1622float2(*(__nv_bfloat162*)&ub.w);
                    s += f0.x*rb0.x + f0.y*rb0.y + f1.x*rb0.z + f1.y*rb0.w
                       + f2.x*rb1.x + f2.y*rb1.y + f3.x*rb1.z + f3.y*rb1.w;
                }
                s = wredsum(s);
                if (lane == 0) { float e = expf(s); g_elog[v] = e; psum += e; }
            }
            if (lane == 0) sh_ws[wid] = psum;
        }
        __syncthreads();
        if (t > 0 && tid == 0) {
            float s = 0.f;
            for (int k = 0; k < NWPB; k++) s += sh_ws[k];
            g_bsum[bid] = s;
        }
        gsync(++ph);

        // ---------------- Seg2 ----------------
        if (t > 0 && wid == 0) {
            float s = red148(g_bsum, lane);
            if (lane == 0) sh_inv = 1.f / s;
        }
        if (t < LL) {   // v_r @ h_new and w_a @ h_new tasks
            const int totB = n_m*8 + n_j*2;
            for (int task = wid; task < totB; task += NWPB) {
                if (task < n_m*8) {
                    const int i = task >> 3, sub = task & 7, half = sub >> 2, ch = sub & 3;
                    const int j = bid + i*GRID;
                    const float4* row4 = (const float4*)v_r_w + (size_t)(j + half*HD)*(D4/4);
                    const int q0 = ch*128 + lane;
                    float s = 0.f;
#pragma unroll
                    for (int it = 0; it < 4; it++) {
                        int q = q0 + 32*it; float4 w4 = row4[q], b = dnxt4[q]; FMA4(s, w4, b);
                    }
                    s = wredsum(s);
                    if (lane == 0) sh_part[task] = s;
                } else {
                    const int u = task - n_m*8;
                    const int i = u >> 1, ch = u & 1;
                    const int jr = bid + i*GRID;
                    const float4* row4 = (const float4*)w_a_w + (size_t)jr*(D2/4);
                    const int q0 = ch*128 + lane;
                    float sa = 0.f, sb = 0.f;
#pragma unroll
                    for (int it = 0; it < 4; it++) {
                        int q = q0 + 32*it; float4 w4 = row4[q];
                        float4 x = dnxt4[q], y = dnxt4[q + 256];
                        FMA4(sa, w4, x); FMA4(sb, w4, y);
                    }
                    sa = wredsum(sa); sb = wredsum(sb);
                    if (lane == 0) { sh_part[64 + u] = sa; sh_part[96 + u] = sb; }
                }
            }
        }
        __syncthreads();
        if (t < LL) {
            if (tid < n_j) {                      // per-row tanh for s(t+1)
                const int jr = bid + tid*GRID;
                float uv = g_uah[jr], vw0 = v_w[jr];
                float t0 = sh_part[64 + tid*2] + sh_part[64 + tid*2 + 1];
                float t1 = sh_part[96 + tid*2] + sh_part[96 + tid*2 + 1];
                sh_part[128 + tid] = vw0 * tanhf(t0 + uv);
                sh_part[160 + tid] = vw0 * tanhf(t1 + uv);
            } else if (tid >= 32 && tid < 32 + n_m) {
                const int i = tid - 32, j = bid + i*GRID;
                const float* p = sh_part + i*8;
                float A = g_r1[j]      + p[0] + p[1] + p[2] + p[3];
                float B = g_r1[j + HD] + p[4] + p[5] + p[6] + p[7];
                g_rmax[j] = fmaxf(A, B);
            }
        }
        __syncthreads();
        if (t < LL && tid == 0) {
            float A = 0.f, B = 0.f;
            for (int i = 0; i < n_j; i++) { A += sh_part[128 + i]; B += sh_part[160 + i]; }
            g_spart2[bid] = A; g_spart2[GRID + bid] = B;
        }
        if (t > 0) {    // normalize + emit row t-1
            const float inv = sh_inv;
            float* orow = out + (size_t)(t - 1)*VV;
            for (int v = bid*TPB + tid; v < VV; v += NT) orow[v] = g_elog[v] * inv;
        }
        gsync(++ph);

        if (t < LL) cur ^= 1;
    }
}

extern "C" void kernel_launch(void* const* d_in, const int* in_sizes, int n_in,
                              void* d_out, int out_size) {
    (void)in_sizes; (void)n_in; (void)out_size;
    init_bar_kernel<<<1, 1>>>();
    decoder_kernel<<<GRID, TPB>>>(
        (const float*)d_in[0],  (const float*)d_in[1],  (const float*)d_in[2],
        (const float*)d_in[3],  (const float*)d_in[4],  (const float*)d_in[5],
        (const float*)d_in[6],  (const float*)d_in[7],  (const float*)d_in[8],
        (const float*)d_in[9],  (const float*)d_in[10], (const float*)d_in[11],
        (const float*)d_in[12], (const float*)d_in[13], (const float*)d_in[14],
        (const float*)d_in[15], (float*)d_out);
}

// round 14
// speedup vs baseline: 1.3009x; 1.3009x over previous
#include <cuda_runtime.h>
#include <cuda_bf16.h>
#include <math.h>

#define GRID 148
#define TPB  512
#define NWPB (TPB/32)            /* 16 warps per block */
#define NWARP (GRID*NWPB)        /* 2368 */
#define NT    (GRID*TPB)         /* 75776 */

#define HD   512
#define D2   1024
#define D4   2048
#define VV   32000
#define MQ   32
#define NP   4096
#define LL   64
#define G6   (3*D4)              /* 6144 GRU gate rows */

// ---------------- device scratch (no allocation allowed) ----------------
__device__ __align__(16) float g_h[D2];
__device__ __align__(16) float g_hpart[GRID*D2];
__device__ __align__(16) float g_uah[D2];
__device__ __align__(16) float g_d[2][D4];
__device__ __align__(16) float g_r1[D2];
__device__ __align__(16) float g_rmax[HD];
__device__ __align__(16) float g_elog[VV];
__device__ __align__(16) float g_gx[LL*G6];     // precomputed W_ih[:, :D2]@w_t + b_ih
__device__ __align__(16) float g_wrx[LL*D2];    // precomputed w_r@w_t
__device__ __align__(16) __nv_bfloat16 g_wo16[(size_t)VV*HD];   // 32.75 MB bf16 vocab weights
__device__ float g_spart2[2*GRID];
__device__ float g_bsum[GRID];
__device__ unsigned g_bar;

__global__ void init_bar_kernel() { g_bar = 0u; }

__device__ __forceinline__ float wredsum(float v) {
#pragma unroll
    for (int o = 16; o; o >>= 1) v += __shfl_xor_sync(0xffffffffu, v, o);
    return v;
}

__device__ __forceinline__ void gsync(unsigned phase) {
    __syncthreads();
    if (threadIdx.x == 0) {
        __threadfence();
        atomicAdd(&g_bar, 1u);
        const unsigned target = (unsigned)GRID * phase;
        while (*((volatile unsigned*)&g_bar) < target) __nanosleep(32);
        __threadfence();
    }
    __syncthreads();
}

__device__ __forceinline__ float red148(const float* __restrict__ p, int lane) {
    float s = 0.f;
#pragma unroll
    for (int i = 0; i < 5; i++) { int idx = lane + 32*i; if (idx < GRID) s += p[idx]; }
    return wredsum(s);
}

#define FMA4(acc, a, b) (acc) += (a).x*(b).x + (a).y*(b).y + (a).z*(b).z + (a).w*(b).w

// bf16x8 (uint4) dot fp32x8 (two float4)
__device__ __forceinline__ float dot_bf16_8(uint4 u, float4 r0, float4 r1) {
    float2 f0 = __bfloat1622float2(*(__nv_bfloat162*)&u.x);
    float2 f1 = __bfloat1622float2(*(__nv_bfloat162*)&u.y);
    float2 f2 = __bfloat1622float2(*(__nv_bfloat162*)&u.z);
    float2 f3 = __bfloat1622float2(*(__nv_bfloat162*)&u.w);
    return f0.x*r0.x + f0.y*r0.y + f1.x*r0.z + f1.y*r0.w
         + f2.x*r1.x + f2.y*r1.y + f3.x*r1.z + f3.y*r1.w;
}

__global__ __launch_bounds__(TPB, 1)
void decoder_kernel(const float* __restrict__ h_q,   const float* __restrict__ h_p,
                    const float* __restrict__ ans,   const float* __restrict__ v_w,
                    const float* __restrict__ w_d_w, const float* __restrict__ w_d_b,
                    const float* __restrict__ w_a_w, const float* __restrict__ u_a_w,
                    const float* __restrict__ w_r_w, const float* __restrict__ u_r_w,
                    const float* __restrict__ v_r_w, const float* __restrict__ w_o_w,
                    const float* __restrict__ gwih,  const float* __restrict__ gwhh,
                    const float* __restrict__ gbih,  const float* __restrict__ gbhh,
                    float* __restrict__ out)
{
    const int tid  = threadIdx.x;
    const int lane = tid & 31;
    const int wid  = tid >> 5;
    const int bid  = blockIdx.x;
    const int gw   = bid * NWPB + wid;
    unsigned ph = 0;

    __shared__ float sh_part[384];
    __shared__ float sh_ws[NWPB];
    __shared__ float sh_a0, sh_a1, sh_inv;
    __shared__ __align__(16) float sh_rm[HD];

    const int n_k = (bid < 124) ? 14 : 13;   // GRU outputs   (2048)
    const int n_j = (bid < 136) ? 7  : 6;    // r1 / w_a rows (1024)
    const int n_m = (bid < 68)  ? 4  : 3;    // maxout outs   (512)

    // ================= Prologue =================
    // P1: h column partials + d0 + w_o->bf16 + ans-GEMM precompute
    {
        float acc0 = 0.f, acc1 = 0.f;
        const int c0 = tid, c1 = tid + TPB;
        for (int r = bid; r < MQ + NP; r += GRID) {
            const float* row = (r < MQ) ? (h_q + (size_t)r*D2) : (h_p + (size_t)(r - MQ)*D2);
            acc0 += row[c0];
            acc1 += row[c1];
        }
        g_hpart[bid*D2 + c0] = acc0;
        g_hpart[bid*D2 + c1] = acc1;
    }
    if (gw < 2*D2) {   // d0[i][j] = tanh(w_d_w[j] . src_i + b[j])
        const int i = gw >> 10, j = gw & (D2-1);
        const float4* src = (const float4*)(i == 0 ? h_q : h_p);
        const float4* wr  = (const float4*)(w_d_w + (size_t)j*D2);
        float s = 0.f;
        for (int q = lane; q < D2/4; q += 32) { float4 a = wr[q], b = src[q]; FMA4(s, a, b); }
        s = wredsum(s);
        if (lane == 0) g_d[0][i*D2 + j] = tanhf(s + w_d_b[j]);
    }
    for (int i = bid*TPB + tid; i < VV*HD/4; i += NT) {   // fp32 -> bf16
        float4 f = ((const float4*)w_o_w)[i];
        __nv_bfloat162 lo = __floats2bfloat162_rn(f.x, f.y);
        __nv_bfloat162 hi = __floats2bfloat162_rn(f.z, f.w);
        uint2 u; u.x = *(unsigned*)&lo; u.y = *(unsigned*)&hi;
        ((uint2*)g_wo16)[i] = u;
    }
    {   // Precompute g_gx / g_wrx: task = (row, 16-step t-chunk)
        const float4* ans4 = (const float4*)ans;
        const int NG = G6*4, NW = D2*4;
        for (int T = gw; T < NG + NW; T += NWARP) {
            const bool isg = (T < NG);
            const int  T2  = isg ? T : (T - NG);
            const int  row = T2 >> 2;
            const int  t0  = (T2 & 3) * 16;
            const float4* row4 = isg ? ((const float4*)gwih + (size_t)row*(D4/4))
                                     : ((const float4*)w_r_w + (size_t)row*(D2/4));
            float4 w[8];
#pragma unroll
            for (int j = 0; j < 8; j++) w[j] = row4[lane + 32*j];
#pragma unroll
            for (int tt = 0; tt < 16; tt++) {
                const int t = t0 + tt;
                const float4* a4 = ans4 + (size_t)t*(D2/4);
                float s = 0.f;
#pragma unroll
                for (int j = 0; j < 8; j++) { float4 b = a4[lane + 32*j]; FMA4(s, w[j], b); }
                s = wredsum(s);
                if (lane == 0) {
                    if (isg) g_gx[t*G6 + row] = s + gbih[row];
                    else     g_wrx[t*D2 + row] = s;
                }
            }
        }
    }
    gsync(++ph);

    // P2: reduce column partials -> g_h
    for (int j = bid*TPB + tid; j < D2; j += NT) {
        float s = 0.f;
        for (int b = 0; b < GRID; b++) s += g_hpart[b*D2 + j];
        g_h[j] = s;
    }
    gsync(++ph);

    // P3: u_a_h = u_a_w @ h
    if (gw < D2) {
        const float4* wr = (const float4*)(u_a_w + (size_t)gw*D2);
        const float4* hv = (const float4*)g_h;
        float s = 0.f;
        for (int q = lane; q < D2/4; q += 32) { float4 a = wr[q], b = hv[q]; FMA4(s, a, b); }
        s = wredsum(s);
        if (lane == 0) g_uah[gw] = s;
    }
    gsync(++ph);

    // P4: attention score partials for d0 -> g_spart2
    {
        float s0p = 0.f, s1p = 0.f;
        if (gw < D2) {
            const int j = gw;
            const float4* wa  = (const float4*)(w_a_w + (size_t)j*D2);
            const float4* dlo = (const float4*)g_d[0];
            const float4* dhi = dlo + 256;
            float a = 0.f, b = 0.f;
            for (int q = lane; q < 256; q += 32) {
                float4 w4 = wa[q], x = dlo[q], y = dhi[q];
                FMA4(a, w4, x); FMA4(b, w4, y);
            }
            a = wredsum(a); b = wredsum(b);
            if (lane == 0) {
                float uv = g_uah[j], vw0 = v_w[j];
                s0p = vw0 * tanhf(a + uv);
                s1p = vw0 * tanhf(b + uv);
            }
        }
        if (lane == 0) { sh_part[wid] = s0p; sh_part[32 + wid] = s1p; }
        __syncthreads();
        if (tid == 0) {
            float A = 0.f, B = 0.f;
            for (int k = 0; k < NWPB; k++) { A += sh_part[k]; B += sh_part[32 + k]; }
            g_spart2[bid] = A; g_spart2[GRID + bid] = B;
        }
    }
    gsync(++ph);

    // ================= decode loop: 3 grid barriers / step (R9 structure) =================
    int cur = 0;
    for (int t = 0; t < LL; ++t) {
        const float*  dcur  = g_d[cur];
        const float4* dcur4 = (const float4*)dcur;
        float*        dnxt  = g_d[cur ^ 1];
        const float4* dnxt4 = (const float4*)dnxt;

        // a(t) from s-partials (warp-0 deterministic reduce, redundant per block)
        if (wid == 0) {
            float s0 = red148(g_spart2, lane);
            float s1 = red148(g_spart2 + GRID, lane);
            if (lane == 0) {
                float mx = fmaxf(s0, s1);
                float e0 = expf(s0 - mx), e1 = expf(s1 - mx);
                float inv = 1.f / (e0 + e1);
                sh_a0 = e0 * inv; sh_a1 = e1 * inv;
            }
        }
        __syncthreads();
        const float a0 = sh_a0, a1 = sh_a1;

        // ---- Segment A: GRU (c-half ih + all hh) + u_r@c (w-parts precomputed) ----
        {
            const int totA = n_k*18 + n_j*2;
            for (int task = wid; task < totA; task += NWPB) {
                float s = 0.f;
                if (task < n_k*18) {
                    const int i = task / 18, sub = task - i*18;
                    const int g = sub / 6, sg = sub - g*6;
                    const int k = bid + i*GRID;
                    if (sg < 2) {   // W_ih row, c-half columns [1024,2048)
                        const float4* row4 = (const float4*)gwih + (size_t)(g*D4 + k)*(D4/4);
                        const int q0 = 256 + sg*128 + lane;
#pragma unroll
                        for (int it = 0; it < 4; it++) {
                            int q = q0 + 32*it; float4 w4 = row4[q];
                            float4 da = dcur4[q - 256], db = dcur4[q], b;
                            b.x = a0*da.x + a1*db.x; b.y = a0*da.y + a1*db.y;
                            b.z = a0*da.z + a1*db.z; b.w = a0*da.w + a1*db.w;
                            FMA4(s, w4, b);
                        }
                    } else {        // W_hh row, chunk sg-2
                        const float4* row4 = (const float4*)gwhh + (size_t)(g*D4 + k)*(D4/4);
                        const int q0 = (sg - 2)*128 + lane;
#pragma unroll
                        for (int it = 0; it < 4; it++) {
                            int q = q0 + 32*it; float4 w4 = row4[q], b = dcur4[q]; FMA4(s, w4, b);
                        }
                    }
                } else {            // u_r @ c
                    const int u = task - n_k*18, i = u >> 1, ch = u & 1;
                    const int j = bid + i*GRID;
                    const float4* row4 = (const float4*)u_r_w + (size_t)j*(D2/4);
                    const int q0 = ch*128 + lane;
#pragma unroll
                    for (int it = 0; it < 4; it++) {
                        int q = q0 + 32*it; float4 w4 = row4[q];
                        float4 da = dcur4[q], db = dcur4[q + 256], b;
                        b.x = a0*da.x + a1*db.x; b.y = a0*da.y + a1*db.y;
                        b.z = a0*da.z + a1*db.z; b.w = a0*da.w + a1*db.w;
                        FMA4(s, w4, b);
                    }
                }
                s = wredsum(s);
                if (lane == 0) sh_part[task] = s;
            }
            __syncthreads();
            if (tid < n_k) {                      // fixed-order GRU combine
                const int k = bid + tid*GRID;
                const float* p = sh_part + tid*18;
                const float* gx = g_gx + t*G6;
                float i0 = gx[k]        + p[0]  + p[1];
                float h0 = p[2]+p[3]+p[4]+p[5]     + gbhh[k];
                float i1 = gx[D4 + k]   + p[6]  + p[7];
                float h1 = p[8]+p[9]+p[10]+p[11]   + gbhh[D4 + k];
                float i2 = gx[2*D4 + k] + p[12] + p[13];
                float h2 = p[14]+p[15]+p[16]+p[17] + gbhh[2*D4 + k];
                float r = 1.f / (1.f + expf(-(i0 + h0)));
                float z = 1.f / (1.f + expf(-(i1 + h1)));
                float n = tanhf(i2 + r * h2);
                dnxt[k] = (1.f - z) * n + z * dcur[k];
            } else if (tid >= 64 && tid < 64 + n_j) {
                const int i = tid - 64, j = bid + i*GRID;
                const float* p = sh_part + n_k*18 + i*2;
                g_r1[j] = g_wrx[t*D2 + j] + p[0] + p[1];
            }
        }
        gsync(++ph);   // alpha: h_new, r1 ready

        // ---- Segment B: v_r@h_new + maxout, and attention scores for t+1 ----
        {
            const int totB = n_m*8 + n_j*2;
            for (int task = wid; task < totB; task += NWPB) {
                if (task < n_m*8) {
                    const int i = task >> 3, sub = task & 7, half = sub >> 2, ch = sub & 3;
                    const int j = bid + i*GRID;
                    const float4* row4 = (const float4*)v_r_w + (size_t)(j + half*HD)*(D4/4);
                    const int q0 = ch*128 + lane;
                    float s = 0.f;
#pragma unroll
                    for (int it = 0; it < 4; it++) {
                        int q = q0 + 32*it; float4 w4 = row4[q], b = dnxt4[q]; FMA4(s, w4, b);
                    }
                    s = wredsum(s);
                    if (lane == 0) sh_part[task] = s;
                } else {
                    const int u = task - n_m*8;
                    const int i = u >> 1, ch = u & 1;
                    const int jr = bid + i*GRID;
                    const float4* row4 = (const float4*)w_a_w + (size_t)jr*(D2/4);
                    const int q0 = ch*128 + lane;
                    float sa = 0.f, sb = 0.f;
#pragma unroll
                    for (int it = 0; it < 4; it++) {
                        int q = q0 + 32*it; float4 w4 = row4[q];
                        float4 x = dnxt4[q], y = dnxt4[q + 256];
                        FMA4(sa, w4, x); FMA4(sb, w4, y);
                    }
                    sa = wredsum(sa); sb = wredsum(sb);
                    if (lane == 0) { sh_part[64 + u] = sa; sh_part[96 + u] = sb; }
                }
            }
            __syncthreads();
            if (tid < n_j) {                      // per-row tanh for s(t+1)
                const int jr = bid + tid*GRID;
                float uv = g_uah[jr], vw0 = v_w[jr];
                float t0 = sh_part[64 + tid*2] + sh_part[64 + tid*2 + 1];
                float t1 = sh_part[96 + tid*2] + sh_part[96 + tid*2 + 1];
                sh_part[128 + tid] = vw0 * tanhf(t0 + uv);
                sh_part[160 + tid] = vw0 * tanhf(t1 + uv);
            } else if (tid >= 32 && tid < 32 + n_m) {
                const int i = tid - 32, j = bid + i*GRID;
                const float* p = sh_part + i*8;
                float A = g_r1[j]      + p[0] + p[1] + p[2] + p[3];
                float B = g_r1[j + HD] + p[4] + p[5] + p[6] + p[7];
                g_rmax[j] = fmaxf(A, B);
            }
            __syncthreads();
            if (tid == 0) {
                float A = 0.f, B = 0.f;
                for (int i = 0; i < n_j; i++) { A += sh_part[128 + i]; B += sh_part[160 + i]; }
                g_spart2[bid] = A; g_spart2[GRID + bid] = B;
            }
        }
        gsync(++ph);   // beta: rmax, s-partials ready

        // ---- Segment C: vocab logits (bf16, 2 rows/iter) + exp + block partial sums ----
        {
            for (int v = tid; v < HD; v += TPB) sh_rm[v] = g_rmax[v];
            __syncthreads();
            float4 ra0 = *(const float4*)(sh_rm + lane*8);
            float4 ra1 = *(const float4*)(sh_rm + lane*8 + 4);
            float4 rb0 = *(const float4*)(sh_rm + (lane + 32)*8);
            float4 rb1 = *(const float4*)(sh_rm + (lane + 32)*8 + 4);
            float psum = 0.f;
            for (int v = gw; v < VV; v += 2*NWARP) {
                const int v2 = v + NWARP;
                const uint4* woA = (const uint4*)(g_wo16 + (size_t)v*HD);
                uint4 ua = woA[lane], ub = woA[lane + 32];
                uint4 uc, ud;
                const bool has2 = (v2 < VV);
                if (has2) {
                    const uint4* woB = (const uint4*)(g_wo16 + (size_t)v2*HD);
                    uc = woB[lane]; ud = woB[lane + 32];
                }
                float s1 = dot_bf16_8(ua, ra0, ra1) + dot_bf16_8(ub, rb0, rb1);
                s1 = wredsum(s1);
                if (lane == 0) { float e = expf(s1); g_elog[v] = e; psum += e; }
                if (has2) {
                    float s2 = dot_bf16_8(uc, ra0, ra1) + dot_bf16_8(ud, rb0, rb1);
                    s2 = wredsum(s2);
                    if (lane == 0) { float e = expf(s2); g_elog[v2] = e; psum += e; }
                }
            }
            if (lane == 0) sh_ws[wid] = psum;
            __syncthreads();
            if (tid == 0) {
                float s = 0.f;
                for (int k = 0; k < NWPB; k++) s += sh_ws[k];
                g_bsum[bid] = s;
            }
        }
        gsync(++ph);   // gamma: exp sums ready

        // ---- Segment D: normalize + emit (no trailing barrier needed) ----
        if (wid == 0) {
            float s = red148(g_bsum, lane);
            if (lane == 0) sh_inv = 1.f / s;
        }
        __syncthreads();
        const float inv = sh_inv;
        float* orow = out + (size_t)t*VV;
        for (int v = bid*TPB + tid; v < VV; v += NT) orow[v] = g_elog[v] * inv;

        cur ^= 1;
    }
}

extern "C" void kernel_launch(void* const* d_in, const int* in_sizes, int n_in,
                              void* d_out, int out_size) {
    (void)in_sizes; (void)n_in; (void)out_size;
    init_bar_kernel<<<1, 1>>>();
    decoder_kernel<<<GRID, TPB>>>(
        (const float*)d_in[0],  (const float*)d_in[1],  (const float*)d_in[2],
        (const float*)d_in[3],  (const float*)d_in[4],  (const float*)d_in[5],
        (const float*)d_in[6],  (const float*)d_in[7],  (const float*)d_in[8],
        (const float*)d_in[9],  (const float*)d_in[10], (const float*)d_in[11],
        (const float*)d_in[12], (const float*)d_in[13], (const float*)d_in[14],
        (const float*)d_in[15], (float*)d_out);
}

// round 16
// speedup vs baseline: 1.3371x; 1.0278x over previous
#include <cuda_runtime.h>
#include <cuda_bf16.h>
#include <math.h>

#define GRID 296                 /* 2 CTAs per SM on 148 SMs */
#define TPB  512
#define NWPB (TPB/32)            /* 16 warps per block */
#define NWARP (GRID*NWPB)        /* 4736 */
#define NT    (GRID*TPB)         /* 151552 */

#define HD   512
#define D2   1024
#define D4   2048
#define VV   32000
#define MQ   32
#define NP   4096
#define LL   64
#define G6   (3*D4)              /* 6144 GRU gate rows */

// ---------------- device scratch (no allocation allowed) ----------------
__device__ __align__(16) float g_h[D2];
__device__ __align__(16) float g_hpart[GRID*D2];
__device__ __align__(16) float g_uah[D2];
__device__ __align__(16) float g_d[2][D4];
__device__ __align__(16) float g_r1[D2];
__device__ __align__(16) float g_rmax[HD];
__device__ __align__(16) float g_elog[VV];
__device__ __align__(16) float g_gx[LL*G6];     // precomputed W_ih[:, :D2]@w_t + b_ih
__device__ __align__(16) float g_wrx[LL*D2];    // precomputed w_r@w_t
__device__ __align__(16) __nv_bfloat16 g_wo16[(size_t)VV*HD];   // 32.75 MB bf16 vocab weights
__device__ float g_spart2[2*GRID];
__device__ float g_bsum[GRID];
__device__ unsigned g_bar;

__global__ void init_bar_kernel() { g_bar = 0u; }

__device__ __forceinline__ float wredsum(float v) {
#pragma unroll
    for (int o = 16; o; o >>= 1) v += __shfl_xor_sync(0xffffffffu, v, o);
    return v;
}

__device__ __forceinline__ void gsync(unsigned phase) {
    __syncthreads();
    if (threadIdx.x == 0) {
        __threadfence();
        atomicAdd(&g_bar, 1u);
        const unsigned target = (unsigned)GRID * phase;
        while (*((volatile unsigned*)&g_bar) < target) __nanosleep(32);
        __threadfence();
    }
    __syncthreads();
}

// deterministic GRID-wide sum on warp 0 (all lanes return full sum)
__device__ __forceinline__ float redG(const float* __restrict__ p, int lane) {
    float s = 0.f;
#pragma unroll
    for (int i = 0; i < (GRID + 31)/32; i++) {
        int idx = lane + 32*i; if (idx < GRID) s += p[idx];
    }
    return wredsum(s);
}

#define FMA4(acc, a, b) (acc) += (a).x*(b).x + (a).y*(b).y + (a).z*(b).z + (a).w*(b).w

// bf16x8 (uint4) dot fp32x8 (two float4)
__device__ __forceinline__ float dot_bf16_8(uint4 u, float4 r0, float4 r1) {
    float2 f0 = __bfloat1622float2(*(__nv_bfloat162*)&u.x);
    float2 f1 = __bfloat1622float2(*(__nv_bfloat162*)&u.y);
    float2 f2 = __bfloat1622float2(*(__nv_bfloat162*)&u.z);
    float2 f3 = __bfloat1622float2(*(__nv_bfloat162*)&u.w);
    return f0.x*r0.x + f0.y*r0.y + f1.x*r0.z + f1.y*r0.w
         + f2.x*r1.x + f2.y*r1.y + f3.x*r1.z + f3.y*r1.w;
}

__global__ __launch_bounds__(TPB, 2)
void decoder_kernel(const float* __restrict__ h_q,   const float* __restrict__ h_p,
                    const float* __restrict__ ans,   const float* __restrict__ v_w,
                    const float* __restrict__ w_d_w, const float* __restrict__ w_d_b,
                    const float* __restrict__ w_a_w, const float* __restrict__ u_a_w,
                    const float* __restrict__ w_r_w, const float* __restrict__ u_r_w,
                    const float* __restrict__ v_r_w, const float* __restrict__ w_o_w,
                    const float* __restrict__ gwih,  const float* __restrict__ gwhh,
                    const float* __restrict__ gbih,  const float* __restrict__ gbhh,
                    float* __restrict__ out)
{
    const int tid  = threadIdx.x;
    const int lane = tid & 31;
    const int wid  = tid >> 5;
    const int bid  = blockIdx.x;
    const int gw   = bid * NWPB + wid;
    unsigned ph = 0;

    __shared__ float sh_part[384];
    __shared__ float sh_ws[NWPB];
    __shared__ float sh_a0, sh_a1, sh_inv;
    __shared__ __align__(16) float sh_rm[HD];

    // per-block output counts (round-robin j = bid + i*GRID)
    const int n_k = (bid < 272) ? 7 : 6;     // GRU outputs   (2048 = 6*296+272)
    const int n_j = (bid < 136) ? 4 : 3;     // r1 / w_a rows (1024 = 3*296+136)
    const int n_m = (bid < 216) ? 2 : 1;     // maxout outs   (512  = 1*296+216)

    // ================= Prologue =================
    // P1: h column partials + d0 + w_o->bf16 + ans-GEMM precompute
    {
        float acc0 = 0.f, acc1 = 0.f;
        const int c0 = tid, c1 = tid + TPB;
        for (int r = bid; r < MQ + NP; r += GRID) {
            const float* row = (r < MQ) ? (h_q + (size_t)r*D2) : (h_p + (size_t)(r - MQ)*D2);
            acc0 += row[c0];
            acc1 += row[c1];
        }
        g_hpart[bid*D2 + c0] = acc0;
        g_hpart[bid*D2 + c1] = acc1;
    }
    if (gw < 2*D2) {   // d0[i][j] = tanh(w_d_w[j] . src_i + b[j])
        const int i = gw >> 10, j = gw & (D2-1);
        const float4* src = (const float4*)(i == 0 ? h_q : h_p);
        const float4* wr  = (const float4*)(w_d_w + (size_t)j*D2);
        float s = 0.f;
        for (int q = lane; q < D2/4; q += 32) { float4 a = wr[q], b = src[q]; FMA4(s, a, b); }
        s = wredsum(s);
        if (lane == 0) g_d[0][i*D2 + j] = tanhf(s + w_d_b[j]);
    }
    for (int i = bid*TPB + tid; i < VV*HD/4; i += NT) {   // fp32 -> bf16
        float4 f = ((const float4*)w_o_w)[i];
        __nv_bfloat162 lo = __floats2bfloat162_rn(f.x, f.y);
        __nv_bfloat162 hi = __floats2bfloat162_rn(f.z, f.w);
        uint2 u; u.x = *(unsigned*)&lo; u.y = *(unsigned*)&hi;
        ((uint2*)g_wo16)[i] = u;
    }
    {   // Precompute g_gx / g_wrx: task = (row, 16-step t-chunk)
        const float4* ans4 = (const float4*)ans;
        const int NG = G6*4, NW = D2*4;
        for (int T = gw; T < NG + NW; T += NWARP) {
            const bool isg = (T < NG);
            const int  T2  = isg ? T : (T - NG);
            const int  row = T2 >> 2;
            const int  t0  = (T2 & 3) * 16;
            const float4* row4 = isg ? ((const float4*)gwih + (size_t)row*(D4/4))
                                     : ((const float4*)w_r_w + (size_t)row*(D2/4));
            for (int tt = 0; tt < 16; tt++) {
                const int t = t0 + tt;
                const float4* a4 = ans4 + (size_t)t*(D2/4);
                float s = 0.f;
#pragma unroll
                for (int j = 0; j < 8; j++) {
                    float4 a = row4[lane + 32*j];
                    float4 b = a4[lane + 32*j];
                    FMA4(s, a, b);
                }
                s = wredsum(s);
                if (lane == 0) {
                    if (isg) g_gx[t*G6 + row] = s + gbih[row];
                    else     g_wrx[t*D2 + row] = s;
                }
            }
        }
    }
    gsync(++ph);

    // P2: reduce column partials -> g_h
    for (int j = bid*TPB + tid; j < D2; j += NT) {
        float s = 0.f;
        for (int b = 0; b < GRID; b++) s += g_hpart[b*D2 + j];
        g_h[j] = s;
    }
    gsync(++ph);

    // P3: u_a_h = u_a_w @ h
    if (gw < D2) {
        const float4* wr = (const float4*)(u_a_w + (size_t)gw*D2);
        const float4* hv = (const float4*)g_h;
        float s = 0.f;
        for (int q = lane; q < D2/4; q += 32) { float4 a = wr[q], b = hv[q]; FMA4(s, a, b); }
        s = wredsum(s);
        if (lane == 0) g_uah[gw] = s;
    }
    gsync(++ph);

    // P4: attention score partials for d0 -> g_spart2
    {
        float s0p = 0.f, s1p = 0.f;
        if (gw < D2) {
            const int j = gw;
            const float4* wa  = (const float4*)(w_a_w + (size_t)j*D2);
            const float4* dlo = (const float4*)g_d[0];
            const float4* dhi = dlo + 256;
            float a = 0.f, b = 0.f;
            for (int q = lane; q < 256; q += 32) {
                float4 w4 = wa[q], x = dlo[q], y = dhi[q];
                FMA4(a, w4, x); FMA4(b, w4, y);
            }
            a = wredsum(a); b = wredsum(b);
            if (lane == 0) {
                float uv = g_uah[j], vw0 = v_w[j];
                s0p = vw0 * tanhf(a + uv);
                s1p = vw0 * tanhf(b + uv);
            }
        }
        if (lane == 0) { sh_part[wid] = s0p; sh_part[32 + wid] = s1p; }
        __syncthreads();
        if (tid == 0) {
            float A = 0.f, B = 0.f;
            for (int k = 0; k < NWPB; k++) { A += sh_part[k]; B += sh_part[32 + k]; }
            g_spart2[bid] = A; g_spart2[GRID + bid] = B;
        }
    }
    gsync(++ph);

    // ================= decode loop: 3 grid barriers / step =================
    int cur = 0;
    for (int t = 0; t < LL; ++t) {
        const float*  dcur  = g_d[cur];
        const float4* dcur4 = (const float4*)dcur;
        float*        dnxt  = g_d[cur ^ 1];
        const float4* dnxt4 = (const float4*)dnxt;

        // a(t) from s-partials (warp-0 deterministic reduce, redundant per block)
        if (wid == 0) {
            float s0 = redG(g_spart2, lane);
            float s1 = redG(g_spart2 + GRID, lane);
            if (lane == 0) {
                float mx = fmaxf(s0, s1);
                float e0 = expf(s0 - mx), e1 = expf(s1 - mx);
                float inv = 1.f / (e0 + e1);
                sh_a0 = e0 * inv; sh_a1 = e1 * inv;
            }
        }
        __syncthreads();
        const float a0 = sh_a0, a1 = sh_a1;

        // ---- Segment A: GRU (c-half ih + all hh) + u_r@c (w-parts precomputed) ----
        {
            const int totA = n_k*18 + n_j*2;
            for (int task = wid; task < totA; task += NWPB) {
                float s = 0.f;
                if (task < n_k*18) {
                    const int i = task / 18, sub = task - i*18;
                    const int g = sub / 6, sg = sub - g*6;
                    const int k = bid + i*GRID;
                    if (sg < 2) {   // W_ih row, c-half columns [1024,2048)
                        const float4* row4 = (const float4*)gwih + (size_t)(g*D4 + k)*(D4/4);
                        const int q0 = 256 + sg*128 + lane;
#pragma unroll
                        for (int it = 0; it < 4; it++) {
                            int q = q0 + 32*it; float4 w4 = row4[q];
                            float4 da = dcur4[q - 256], db = dcur4[q], b;
                            b.x = a0*da.x + a1*db.x; b.y = a0*da.y + a1*db.y;
                            b.z = a0*da.z + a1*db.z; b.w = a0*da.w + a1*db.w;
                            FMA4(s, w4, b);
                        }
                    } else {        // W_hh row, chunk sg-2
                        const float4* row4 = (const float4*)gwhh + (size_t)(g*D4 + k)*(D4/4);
                        const int q0 = (sg - 2)*128 + lane;
#pragma unroll
                        for (int it = 0; it < 4; it++) {
                            int q = q0 + 32*it; float4 w4 = row4[q], b = dcur4[q]; FMA4(s, w4, b);
                        }
                    }
                } else {            // u_r @ c
                    const int u = task - n_k*18, i = u >> 1, ch = u & 1;
                    const int j = bid + i*GRID;
                    const float4* row4 = (const float4*)u_r_w + (size_t)j*(D2/4);
                    const int q0 = ch*128 + lane;
#pragma unroll
                    for (int it = 0; it < 4; it++) {
                        int q = q0 + 32*it; float4 w4 = row4[q];
                        float4 da = dcur4[q], db = dcur4[q + 256], b;
                        b.x = a0*da.x + a1*db.x; b.y = a0*da.y + a1*db.y;
                        b.z = a0*da.z + a1*db.z; b.w = a0*da.w + a1*db.w;
                        FMA4(s, w4, b);
                    }
                }
                s = wredsum(s);
                if (lane == 0) sh_part[task] = s;
            }
            __syncthreads();
            if (tid < n_k) {                      // fixed-order GRU combine
                const int k = bid + tid*GRID;
                const float* p = sh_part + tid*18;
                const float* gx = g_gx + t*G6;
                float i0 = gx[k]        + p[0]  + p[1];
                float h0 = p[2]+p[3]+p[4]+p[5]     + gbhh[k];
                float i1 = gx[D4 + k]   + p[6]  + p[7];
                float h1 = p[8]+p[9]+p[10]+p[11]   + gbhh[D4 + k];
                float i2 = gx[2*D4 + k] + p[12] + p[13];
                float h2 = p[14]+p[15]+p[16]+p[17] + gbhh[2*D4 + k];
                float r = 1.f / (1.f + expf(-(i0 + h0)));
                float z = 1.f / (1.f + expf(-(i1 + h1)));
                float n = tanhf(i2 + r * h2);
                dnxt[k] = (1.f - z) * n + z * dcur[k];
            } else if (tid >= 64 && tid < 64 + n_j) {
                const int i = tid - 64, j = bid + i*GRID;
                const float* p = sh_part + n_k*18 + i*2;
                g_r1[j] = g_wrx[t*D2 + j] + p[0] + p[1];
            }
        }
        gsync(++ph);   // alpha: h_new, r1 ready

        // ---- Segment B: v_r@h_new + maxout, and attention scores for t+1 ----
        {
            const int totB = n_m*8 + n_j*2;
            for (int task = wid; task < totB; task += NWPB) {
                if (task < n_m*8) {
                    const int i = task >> 3, sub = task & 7, half = sub >> 2, ch = sub & 3;
                    const int j = bid + i*GRID;
                    const float4* row4 = (const float4*)v_r_w + (size_t)(j + half*HD)*(D4/4);
                    const int q0 = ch*128 + lane;
                    float s = 0.f;
#pragma unroll
                    for (int it = 0; it < 4; it++) {
                        int q = q0 + 32*it; float4 w4 = row4[q], b = dnxt4[q]; FMA4(s, w4, b);
                    }
                    s = wredsum(s);
                    if (lane == 0) sh_part[task] = s;
                } else {
                    const int u = task - n_m*8;
                    const int i = u >> 1, ch = u & 1;
                    const int jr = bid + i*GRID;
                    const float4* row4 = (const float4*)w_a_w + (size_t)jr*(D2/4);
                    const int q0 = ch*128 + lane;
                    float sa = 0.f, sb = 0.f;
#pragma unroll
                    for (int it = 0; it < 4; it++) {
                        int q = q0 + 32*it; float4 w4 = row4[q];
                        float4 x = dnxt4[q], y = dnxt4[q + 256];
                        FMA4(sa, w4, x); FMA4(sb, w4, y);
                    }
                    sa = wredsum(sa); sb = wredsum(sb);
                    if (lane == 0) { sh_part[64 + u] = sa; sh_part[96 + u] = sb; }
                }
            }
            __syncthreads();
            if (tid < n_j) {                      // per-row tanh for s(t+1)
                const int jr = bid + tid*GRID;
                float uv = g_uah[jr], vw0 = v_w[jr];
                float t0 = sh_part[64 + tid*2] + sh_part[64 + tid*2 + 1];
                float t1 = sh_part[96 + tid*2] + sh_part[96 + tid*2 + 1];
                sh_part[128 + tid] = vw0 * tanhf(t0 + uv);
                sh_part[160 + tid] = vw0 * tanhf(t1 + uv);
            } else if (tid >= 32 && tid < 32 + n_m) {
                const int i = tid - 32, j = bid + i*GRID;
                const float* p = sh_part + i*8;
                float A = g_r1[j]      + p[0] + p[1] + p[2] + p[3];
                float B = g_r1[j + HD] + p[4] + p[5] + p[6] + p[7];
                g_rmax[j] = fmaxf(A, B);
            }
            __syncthreads();
            if (tid == 0) {
                float A = 0.f, B = 0.f;
                for (int i = 0; i < n_j; i++) { A += sh_part[128 + i]; B += sh_part[160 + i]; }
                g_spart2[bid] = A; g_spart2[GRID + bid] = B;
            }
        }
        gsync(++ph);   // beta: rmax, s-partials ready

        // ---- Segment C: vocab logits (bf16, 2 rows/iter) + exp + block partial sums ----
        {
            for (int v = tid; v < HD; v += TPB) sh_rm[v] = g_rmax[v];
            __syncthreads();
            float4 ra0 = *(const float4*)(sh_rm + lane*8);
            float4 ra1 = *(const float4*)(sh_rm + lane*8 + 4);
            float4 rb0 = *(const float4*)(sh_rm + (lane + 32)*8);
            float4 rb1 = *(const float4*)(sh_rm + (lane + 32)*8 + 4);
            float psum = 0.f;
            for (int v = gw; v < VV; v += 2*NWARP) {
                const int v2 = v + NWARP;
                const uint4* woA = (const uint4*)(g_wo16 + (size_t)v*HD);
                uint4 ua = woA[lane], ub = woA[lane + 32];
                uint4 uc, ud;
                const bool has2 = (v2 < VV);
                if (has2) {
                    const uint4* woB = (const uint4*)(g_wo16 + (size_t)v2*HD);
                    uc = woB[lane]; ud = woB[lane + 32];
                }
                float s1 = dot_bf16_8(ua, ra0, ra1) + dot_bf16_8(ub, rb0, rb1);
                s1 = wredsum(s1);
                if (lane == 0) { float e = expf(s1); g_elog[v] = e; psum += e; }
                if (has2) {
                    float s2 = dot_bf16_8(uc, ra0, ra1) + dot_bf16_8(ud, rb0, rb1);
                    s2 = wredsum(s2);
                    if (lane == 0) { float e = expf(s2); g_elog[v2] = e; psum += e; }
                }
            }
            if (lane == 0) sh_ws[wid] = psum;
            __syncthreads();
            if (tid == 0) {
                float s = 0.f;
                for (int k = 0; k < NWPB; k++) s += sh_ws[k];
                g_bsum[bid] = s;
            }
        }
        gsync(++ph);   // gamma: exp sums ready

        // ---- Segment D: normalize + emit (no trailing barrier needed) ----
        if (wid == 0) {
            float s = redG(g_bsum, lane);
            if (lane == 0) sh_inv = 1.f / s;
        }
        __syncthreads();
        const float inv = sh_inv;
        float* orow = out + (size_t)t*VV;
        for (int v = bid*TPB + tid; v < VV; v += NT) orow[v] = g_elog[v] * inv;

        cur ^= 1;
    }
}

extern "C" void kernel_launch(void* const* d_in, const int* in_sizes, int n_in,
                              void* d_out, int out_size) {
    (void)in_sizes; (void)n_in; (void)out_size;
    init_bar_kernel<<<1, 1>>>();
    decoder_kernel<<<GRID, TPB>>>(
        (const float*)d_in[0],  (const float*)d_in[1],  (const float*)d_in[2],
        (const float*)d_in[3],  (const float*)d_in[4],  (const float*)d_in[5],
        (const float*)d_in[6],  (const float*)d_in[7],  (const float*)d_in[8],
        (const float*)d_in[9],  (const float*)d_in[10], (const float*)d_in[11],
        (const float*)d_in[12], (const float*)d_in[13], (const float*)d_in[14],
        (const float*)d_in[15], (float*)d_out);
}